// round 1
// baseline (speedup 1.0000x reference)
#include <cuda_runtime.h>
#include <cuda_bf16.h>
#include <math.h>

// Problem dims
#define L_   4
#define D_   1024
#define DK_  64
#define B_   8
#define S_   512
#define FF_  4096
#define BS_  (B_ * S_)           // 4096 rows
#define EPS_ 1e-3f

// -------------------- scratch (device globals; no allocations) ---------------
__device__ float g_x[BS_ * D_];          // activations [4096,1024]
__device__ float g_q[BS_ * DK_];
__device__ float g_k[BS_ * DK_];
__device__ float g_v[BS_ * DK_];
__device__ float g_p[B_ * S_ * S_];      // scores / probs [8,512,512]
__device__ float g_h[BS_ * DK_];         // attention head out
__device__ float g_f[BS_ * FF_];         // ffn hidden [4096,4096]

// -------------------- embedding + positional-scalar bug ----------------------
__global__ void __launch_bounds__(256) embed_kernel(
    const int* __restrict__ seq, const float* __restrict__ emb,
    const float* __restrict__ pes, float* __restrict__ x)
{
    int bs = blockIdx.x;                  // 0..4095
    int s  = bs & (S_ - 1);
    int tok = seq[bs];
    float p = pes[(long)s * D_];          // pes[s, 0] scalar added to all D
    const float4* e = (const float4*)(emb + (long)tok * D_);
    float4* xo = (float4*)(x + (long)bs * D_);
    float4 v = e[threadIdx.x];
    v.x += p; v.y += p; v.z += p; v.w += p;
    xo[threadIdx.x] = v;
}

// -------------------- generic tiled GEMM with fused epilogues ----------------
// C[M,N] = A[M,K] @ W[K,N] (+bias) ; mode 0: bias, 1: bias+relu,
// 2: BN(residual + bias + acc). Batched via blockIdx.z with strides.
// Requires M%64==0, N%64==0, K%16==0 (true for all call sites).
__global__ void __launch_bounds__(256) gemm64(
    const float* __restrict__ A, const float* __restrict__ W,
    const float* __restrict__ bias, float* __restrict__ C,
    int M, int N, int K,
    long sA, long sW, long sC,
    int mode,
    const float* __restrict__ res,
    const float* __restrict__ gamma, const float* __restrict__ beta,
    const float* __restrict__ mean,  const float* __restrict__ var)
{
    __shared__ float As[16][68];   // A^T tile: As[k][m]
    __shared__ float Bs[16][68];   // B tile:   Bs[k][n]

    int bz = blockIdx.z;
    A += bz * sA; W += bz * sW; C += bz * sC;
    if (res) res += bz * sC;

    int row0 = blockIdx.y * 64;
    int col0 = blockIdx.x * 64;
    int tid = threadIdx.x;
    int tx = tid & 15, ty = tid >> 4;

    float acc[4][4];
    #pragma unroll
    for (int i = 0; i < 4; i++)
        #pragma unroll
        for (int j = 0; j < 4; j++) acc[i][j] = 0.f;

    int ar = tid >> 2, ac = (tid & 3) * 4;   // A load: row, 4-col group
    int bk = tid >> 4, bc = (tid & 15) * 4;  // B load: k-row, 4-col group

    for (int k0 = 0; k0 < K; k0 += 16) {
        float4 av = *(const float4*)&A[(long)(row0 + ar) * K + k0 + ac];
        As[ac + 0][ar] = av.x;
        As[ac + 1][ar] = av.y;
        As[ac + 2][ar] = av.z;
        As[ac + 3][ar] = av.w;
        float4 bv = *(const float4*)&W[(long)(k0 + bk) * N + col0 + bc];
        *(float4*)&Bs[bk][bc] = bv;
        __syncthreads();

        #pragma unroll
        for (int kk = 0; kk < 16; kk++) {
            float4 a = *(const float4*)&As[kk][ty * 4];
            float4 b = *(const float4*)&Bs[kk][tx * 4];
            float ai[4] = {a.x, a.y, a.z, a.w};
            float bj[4] = {b.x, b.y, b.z, b.w};
            #pragma unroll
            for (int i = 0; i < 4; i++)
                #pragma unroll
                for (int j = 0; j < 4; j++)
                    acc[i][j] = fmaf(ai[i], bj[j], acc[i][j]);
        }
        __syncthreads();
    }

    int r = row0 + ty * 4, c = col0 + tx * 4;
    #pragma unroll
    for (int i = 0; i < 4; i++) {
        #pragma unroll
        for (int j = 0; j < 4; j++) {
            int cc = c + j;
            float v = acc[i][j] + (bias ? bias[cc] : 0.f);
            if (mode == 1) v = fmaxf(v, 0.f);
            if (mode == 2) {
                v += res[(long)(r + i) * N + cc];
                v = gamma[cc] * (v - mean[cc]) * rsqrtf(var[cc] + EPS_) + beta[cc];
            }
            C[(long)(r + i) * N + cc] = v;
        }
    }
}

// -------------------- attention scores: S[b,q,k] = scale * q.k ---------------
__global__ void __launch_bounds__(1024) score_kernel(
    const float* __restrict__ q, const float* __restrict__ k,
    float* __restrict__ sc)
{
    __shared__ float qs[32][65];
    __shared__ float ks[32][65];
    int b = blockIdx.z;
    int qr = blockIdx.y * 32, kr = blockIdx.x * 32;
    const float* qb = q + (long)b * S_ * DK_;
    const float* kb = k + (long)b * S_ * DK_;

    int tid = threadIdx.y * 32 + threadIdx.x;
    int lr = tid >> 5, lc = tid & 31;
    qs[lr][lc]      = qb[(qr + lr) * DK_ + lc];
    qs[lr][lc + 32] = qb[(qr + lr) * DK_ + lc + 32];
    ks[lr][lc]      = kb[(kr + lr) * DK_ + lc];
    ks[lr][lc + 32] = kb[(kr + lr) * DK_ + lc + 32];
    __syncthreads();

    float acc = 0.f;
    #pragma unroll
    for (int d = 0; d < DK_; d++)
        acc = fmaf(qs[threadIdx.y][d], ks[threadIdx.x][d], acc);

    sc[(long)b * S_ * S_ + (long)(qr + threadIdx.y) * S_ + kr + threadIdx.x] =
        acc * 0.125f;   // 1/sqrt(64)
}

// -------------------- row softmax over 512 -----------------------------------
__global__ void __launch_bounds__(256) softmax512(float* __restrict__ p)
{
    __shared__ float red[256];
    float* r = p + (long)blockIdx.x * S_;
    int t = threadIdx.x;
    float a = r[t], b = r[t + 256];

    red[t] = fmaxf(a, b);
    __syncthreads();
    for (int s = 128; s > 0; s >>= 1) {
        if (t < s) red[t] = fmaxf(red[t], red[t + s]);
        __syncthreads();
    }
    float m = red[0];
    __syncthreads();

    float ea = __expf(a - m), eb = __expf(b - m);
    red[t] = ea + eb;
    __syncthreads();
    for (int s = 128; s > 0; s >>= 1) {
        if (t < s) red[t] += red[t + s];
        __syncthreads();
    }
    float inv = 1.0f / red[0];
    r[t] = ea * inv;
    r[t + 256] = eb * inv;
}

// ------------------------------------------------------------------------------
extern "C" void kernel_launch(void* const* d_in, const int* in_sizes, int n_in,
                              void* d_out, int out_size)
{
    const int*   seq  = (const int*)  d_in[0];
    const float* emb  = (const float*)d_in[1];
    const float* pes  = (const float*)d_in[2];
    const float* wq   = (const float*)d_in[3];
    const float* bq   = (const float*)d_in[4];
    const float* wk   = (const float*)d_in[5];
    const float* bk   = (const float*)d_in[6];
    const float* wv   = (const float*)d_in[7];
    const float* bv   = (const float*)d_in[8];
    const float* wo   = (const float*)d_in[9];
    const float* bo   = (const float*)d_in[10];
    const float* agam = (const float*)d_in[11];
    const float* abet = (const float*)d_in[12];
    const float* amea = (const float*)d_in[13];
    const float* avar = (const float*)d_in[14];
    const float* w1   = (const float*)d_in[15];
    const float* bff1 = (const float*)d_in[16];
    const float* w2   = (const float*)d_in[17];
    const float* bff2 = (const float*)d_in[18];
    const float* fgam = (const float*)d_in[19];
    const float* fbet = (const float*)d_in[20];
    const float* fmea = (const float*)d_in[21];
    const float* fvar = (const float*)d_in[22];
    float* out = (float*)d_out;

    float *x, *q, *k, *v, *p, *h, *f;
    cudaGetSymbolAddress((void**)&x, g_x);
    cudaGetSymbolAddress((void**)&q, g_q);
    cudaGetSymbolAddress((void**)&k, g_k);
    cudaGetSymbolAddress((void**)&v, g_v);
    cudaGetSymbolAddress((void**)&p, g_p);
    cudaGetSymbolAddress((void**)&h, g_h);
    cudaGetSymbolAddress((void**)&f, g_f);

    // 1. embedding + positional-scalar
    embed_kernel<<<BS_, 256>>>(seq, emb, pes, x);

    for (int l = 0; l < L_; l++) {
        const float* wql = wq + (long)l * D_ * DK_;
        const float* wkl = wk + (long)l * D_ * DK_;
        const float* wvl = wv + (long)l * D_ * DK_;
        const float* wol = wo + (long)l * DK_ * D_;
        const float* w1l = w1 + (long)l * D_ * FF_;
        const float* w2l = w2 + (long)l * FF_ * D_;

        dim3 blk(256);

        // QKV projections: [4096,1024] @ [1024,64]
        dim3 gqkv(DK_ / 64, BS_ / 64, 1);
        gemm64<<<gqkv, blk>>>(x, wql, bq + l * DK_, q, BS_, DK_, D_, 0, 0, 0,
                              0, nullptr, nullptr, nullptr, nullptr, nullptr);
        gemm64<<<gqkv, blk>>>(x, wkl, bk + l * DK_, k, BS_, DK_, D_, 0, 0, 0,
                              0, nullptr, nullptr, nullptr, nullptr, nullptr);
        gemm64<<<gqkv, blk>>>(x, wvl, bv + l * DK_, v, BS_, DK_, D_, 0, 0, 0,
                              0, nullptr, nullptr, nullptr, nullptr, nullptr);

        // scores + softmax
        dim3 gsc(S_ / 32, S_ / 32, B_);
        score_kernel<<<gsc, dim3(32, 32)>>>(q, k, p);
        softmax512<<<B_ * S_, 256>>>(p);

        // head = P @ V  (batched: M=512, N=64, K=512)
        dim3 ghd(DK_ / 64, S_ / 64, B_);
        gemm64<<<ghd, blk>>>(p, v, nullptr, h, S_, DK_, S_,
                             (long)S_ * S_, (long)S_ * DK_, (long)S_ * DK_,
                             0, nullptr, nullptr, nullptr, nullptr, nullptr);

        // att out + residual + BN: x = BN(x + h @ wo + bo)
        dim3 gao(D_ / 64, BS_ / 64, 1);
        gemm64<<<gao, blk>>>(h, wol, bo + l * D_, x, BS_, D_, DK_, 0, 0, 0,
                             2, x, agam + l * D_, abet + l * D_,
                             amea + l * D_, avar + l * D_);

        // FFN1: relu(x @ w1 + b1) -> f   [4096,4096]
        dim3 gf1(FF_ / 64, BS_ / 64, 1);
        gemm64<<<gf1, blk>>>(x, w1l, bff1 + l * FF_, f, BS_, FF_, D_, 0, 0, 0,
                             1, nullptr, nullptr, nullptr, nullptr, nullptr);

        // FFN2 + residual + BN: x = BN(x + f @ w2 + b2); last layer -> d_out
        float* dst = (l == L_ - 1) ? out : x;
        dim3 gf2(D_ / 64, BS_ / 64, 1);
        gemm64<<<gf2, blk>>>(f, w2l, bff2 + l * D_, dst, BS_, D_, FF_, 0, 0, 0,
                             2, x, fgam + l * D_, fbet + l * D_,
                             fmea + l * D_, fvar + l * D_);
    }
}

// round 4
// speedup vs baseline: 1.5656x; 1.5656x over previous
#include <cuda_runtime.h>
#include <cuda_bf16.h>
#include <mma.h>
#include <math.h>
#include <stdint.h>

using namespace nvcuda;

// Problem dims
#define L_   4
#define D_   1024
#define DK_  64
#define B_   8
#define S_   512
#define FF_  4096
#define BS_  (B_ * S_)           // 4096 rows
#define NQKV 256                 // padded q|k|v concat width
#define EPS_ 1e-3f

// -------------------- scratch (device globals; no allocations) ---------------
__device__ float g_x[BS_ * D_];            // activations [4096,1024]
__device__ float g_qkv[BS_ * NQKV];        // q|k|v|pad   [4096,256]
__device__ float g_p[B_ * S_ * S_];        // scores / probs
__device__ float g_h[BS_ * DK_];           // attention head out
__device__ float g_f[BS_ * FF_];           // ffn hidden
__device__ float g_vt[B_ * DK_ * S_];      // V^T per batch [64,512]
__device__ float g_w1t[L_ * FF_ * D_];     // w1^T [4096,1024]
__device__ float g_w2t[L_ * D_ * FF_];     // w2^T [1024,4096]
__device__ float g_wot[L_ * D_ * DK_];     // wo^T [1024,64]
__device__ float g_wqkvt[L_ * NQKV * D_];  // packed qkv^T [256,1024]
__device__ float g_bqkv[L_ * NQKV];

__device__ __forceinline__ uint32_t smem_u32(const void* p) {
    uint32_t a;
    asm("{ .reg .u64 t; cvta.to.shared.u64 t, %1; cvt.u32.u64 %0, t; }" : "=r"(a) : "l"(p));
    return a;
}

// ======================= wmma TF32 pipelined GEMM ============================
// C[M, N] = A[M, K(ldA)] @ Bt[N, K(ldB)]^T   (Bt is B transposed, K-major)
// CTA tile: 128 x BN, K chunk 32, 3-stage cp.async pipeline.
// 8 warps (4 m x 2 n); warp tile 32 x (BN/2); wmma m16n16k8 tf32.
// mode 0: +bias   1: +bias, relu   2: BN(res + bias + acc)   3: acc * 0.125
// Requires: K % 32 == 0, rows of A/Bt 16B-aligned, ldC == N.
#define STAGES 3

template<int BN>
__global__ void __launch_bounds__(256) wgemm(
    const float* __restrict__ A, int ldA,
    const float* __restrict__ Bt, int ldB,
    const float* __restrict__ bias, float* __restrict__ C,
    int N, int K, long sA, long sB, long sC,
    int mode,
    const float* __restrict__ res,
    const float* __restrict__ gamma, const float* __restrict__ beta,
    const float* __restrict__ mean,  const float* __restrict__ var)
{
    constexpr int BM = 128, BK = 32, LDS = BK + 4;     // 36 floats/row (144B)
    constexpr int A_STG = BM * LDS;                    // floats
    constexpr int B_STG = BN * LDS;
    constexpr int STG = A_STG + B_STG;
    constexpr int WN = BN / 2;                         // warp n extent
    constexpr int NT = WN / 16;                        // wmma tiles per warp in n

    extern __shared__ float sm[];

    const int tid = threadIdx.x;
    const int wid = tid >> 5;
    const int warp_m = wid & 3;          // 0..3
    const int warp_n = wid >> 2;         // 0..1
    const int m0 = blockIdx.y * BM;
    const int n0 = blockIdx.x * BN;
    const int bz = blockIdx.z;
    A += bz * sA; Bt += bz * sB; C += bz * sC;
    if (res) res += bz * sC;

    const int NK = K >> 5;

    auto load_chunk = [&](int chunk, int stage) {
        float* smA = sm + stage * STG;
        float* smB = smA + A_STG;
        const float* gA = A + (long)m0 * ldA + chunk * 32;
        const float* gB = Bt + (long)n0 * ldB + chunk * 32;
        #pragma unroll
        for (int j = 0; j < 4; j++) {               // A: 128 rows x 8 float4
            int idx = tid + j * 256;
            int r = idx >> 3, c4 = (idx & 7) * 4;
            uint32_t dst = smem_u32(&smA[r * LDS + c4]);
            const float* src = gA + (long)r * ldA + c4;
            asm volatile("cp.async.cg.shared.global [%0], [%1], 16;" :: "r"(dst), "l"(src));
        }
        #pragma unroll
        for (int j = 0; j < BN / 32; j++) {         // B: BN rows x 8 float4
            int idx = tid + j * 256;
            int r = idx >> 3, c4 = (idx & 7) * 4;
            uint32_t dst = smem_u32(&smB[r * LDS + c4]);
            const float* src = gB + (long)r * ldB + c4;
            asm volatile("cp.async.cg.shared.global [%0], [%1], 16;" :: "r"(dst), "l"(src));
        }
        asm volatile("cp.async.commit_group;" ::: "memory");
    };

    wmma::fragment<wmma::accumulator, 16, 16, 8, float> acc[2][NT];
    #pragma unroll
    for (int i = 0; i < 2; i++)
        #pragma unroll
        for (int j = 0; j < NT; j++) wmma::fill_fragment(acc[i][j], 0.f);

    load_chunk(0, 0);
    if (NK > 1) load_chunk(1, 1);

    for (int i = 0; i < NK; i++) {
        if (i < NK - 1) asm volatile("cp.async.wait_group 1;" ::: "memory");
        else            asm volatile("cp.async.wait_group 0;" ::: "memory");
        __syncthreads();

        if (i + 2 < NK) load_chunk(i + 2, (i + 2) % STAGES);

        const float* sA = sm + (i % STAGES) * STG;
        const float* sB = sA + A_STG;

        #pragma unroll
        for (int ks = 0; ks < 4; ks++) {
            int kk = ks * 8;
            wmma::fragment<wmma::matrix_a, 16, 16, 8, wmma::precision::tf32, wmma::row_major> af[2];
            wmma::fragment<wmma::matrix_b, 16, 16, 8, wmma::precision::tf32, wmma::col_major> bf[NT];
            #pragma unroll
            for (int mi = 0; mi < 2; mi++) {
                wmma::load_matrix_sync(af[mi], sA + (warp_m * 32 + mi * 16) * LDS + kk, LDS);
                #pragma unroll
                for (int e = 0; e < af[mi].num_elements; e++)
                    af[mi].x[e] = wmma::__float_to_tf32(af[mi].x[e]);
            }
            #pragma unroll
            for (int nj = 0; nj < NT; nj++) {
                wmma::load_matrix_sync(bf[nj], sB + (warp_n * WN + nj * 16) * LDS + kk, LDS);
                #pragma unroll
                for (int e = 0; e < bf[nj].num_elements; e++)
                    bf[nj].x[e] = wmma::__float_to_tf32(bf[nj].x[e]);
            }
            #pragma unroll
            for (int mi = 0; mi < 2; mi++)
                #pragma unroll
                for (int nj = 0; nj < NT; nj++)
                    wmma::mma_sync(acc[mi][nj], af[mi], bf[nj], acc[mi][nj]);
        }
        __syncthreads();
    }

    // ---------------- epilogue: stage accum tile in smem, fused ops ----------
    float* stg = sm;                     // reuse pipeline buffers (BM*BN <= stages)
    #pragma unroll
    for (int mi = 0; mi < 2; mi++)
        #pragma unroll
        for (int nj = 0; nj < NT; nj++)
            wmma::store_matrix_sync(
                stg + (long)(warp_m * 32 + mi * 16) * BN + warp_n * WN + nj * 16,
                acc[mi][nj], BN, wmma::mem_row_major);
    __syncthreads();

    #pragma unroll
    for (int it = 0; it < BM * BN / 4 / 256; it++) {
        int idx = (tid + it * 256) * 4;
        int r = idx / BN, c = idx % BN;
        int gc = n0 + c;
        float4 o = *(const float4*)&stg[idx];
        if (bias) {
            float4 bb = *(const float4*)&bias[gc];
            o.x += bb.x; o.y += bb.y; o.z += bb.z; o.w += bb.w;
        }
        if (mode == 1) {
            o.x = fmaxf(o.x, 0.f); o.y = fmaxf(o.y, 0.f);
            o.z = fmaxf(o.z, 0.f); o.w = fmaxf(o.w, 0.f);
        } else if (mode == 2) {
            float4 rr = *(const float4*)&res[(long)(m0 + r) * N + gc];
            float4 gg = *(const float4*)&gamma[gc];
            float4 be = *(const float4*)&beta[gc];
            float4 mm = *(const float4*)&mean[gc];
            float4 va = *(const float4*)&var[gc];
            o.x = gg.x * (o.x + rr.x - mm.x) * rsqrtf(va.x + EPS_) + be.x;
            o.y = gg.y * (o.y + rr.y - mm.y) * rsqrtf(va.y + EPS_) + be.y;
            o.z = gg.z * (o.z + rr.z - mm.z) * rsqrtf(va.z + EPS_) + be.z;
            o.w = gg.w * (o.w + rr.w - mm.w) * rsqrtf(va.w + EPS_) + be.w;
        } else if (mode == 3) {
            o.x *= 0.125f; o.y *= 0.125f; o.z *= 0.125f; o.w *= 0.125f;
        }
        *(float4*)&C[(long)(m0 + r) * N + gc] = o;
    }
}

// ======================= small prep / misc kernels ===========================
__global__ void __launch_bounds__(256) embed_kernel(
    const int* __restrict__ seq, const float* __restrict__ emb,
    const float* __restrict__ pes, float* __restrict__ x)
{
    int bs = blockIdx.x;
    int s  = bs & (S_ - 1);
    int tok = seq[bs];
    float p = pes[(long)s * D_];
    const float4* e = (const float4*)(emb + (long)tok * D_);
    float4* xo = (float4*)(x + (long)bs * D_);
    float4 v = e[threadIdx.x];
    v.x += p; v.y += p; v.z += p; v.w += p;
    xo[threadIdx.x] = v;
}

// out[c][r] = in[r][c]; batched by blockIdx.z
__global__ void __launch_bounds__(256) transpose_k(
    const float* __restrict__ in, float* __restrict__ out,
    int R, int C, int ldIn, long sIn, long sOut)
{
    __shared__ float t[32][33];
    in += (long)blockIdx.z * sIn; out += (long)blockIdx.z * sOut;
    int c0 = blockIdx.x * 32, r0 = blockIdx.y * 32;
    int tx = threadIdx.x, ty = threadIdx.y;
    #pragma unroll
    for (int j = 0; j < 32; j += 8)
        t[ty + j][tx] = in[(long)(r0 + ty + j) * ldIn + c0 + tx];
    __syncthreads();
    #pragma unroll
    for (int j = 0; j < 32; j += 8)
        out[(long)(c0 + ty + j) * R + r0 + tx] = t[tx][ty + j];
}

// pack wq|wk|wv -> wqkvt [L][256][1024] (transposed) + bias pack
__global__ void __launch_bounds__(256) qkvpack(
    const float* __restrict__ wq, const float* __restrict__ wk,
    const float* __restrict__ wv, const float* __restrict__ bq,
    const float* __restrict__ bk, const float* __restrict__ bv,
    float* __restrict__ wt, float* __restrict__ bt)
{
    int l = blockIdx.z;
    int n = blockIdx.y;                         // 0..255
    int k = blockIdx.x * 256 + threadIdx.x;     // 0..1023
    const float* src = (n < 64) ? wq : (n < 128) ? wk : (n < 192) ? wv : nullptr;
    int j = n & 63;
    float v = 0.f;
    if (src) v = src[((long)l * D_ + k) * DK_ + j];
    wt[((long)l * NQKV + n) * D_ + k] = v;
    if (blockIdx.x == 0 && threadIdx.x == 0) {
        const float* bs = (n < 64) ? bq : (n < 128) ? bk : (n < 192) ? bv : nullptr;
        bt[l * NQKV + n] = bs ? bs[l * DK_ + j] : 0.f;
    }
}

__global__ void __launch_bounds__(256) softmax512(float* __restrict__ p)
{
    __shared__ float red[256];
    float* r = p + (long)blockIdx.x * S_;
    int t = threadIdx.x;
    float a = r[t], b = r[t + 256];
    red[t] = fmaxf(a, b);
    __syncthreads();
    for (int s = 128; s > 0; s >>= 1) {
        if (t < s) red[t] = fmaxf(red[t], red[t + s]);
        __syncthreads();
    }
    float m = red[0];
    __syncthreads();
    float ea = __expf(a - m), eb = __expf(b - m);
    red[t] = ea + eb;
    __syncthreads();
    for (int s = 128; s > 0; s >>= 1) {
        if (t < s) red[t] += red[t + s];
        __syncthreads();
    }
    float inv = 1.0f / red[0];
    r[t] = ea * inv;
    r[t + 256] = eb * inv;
}

// ------------------------------------------------------------------------------
extern "C" void kernel_launch(void* const* d_in, const int* in_sizes, int n_in,
                              void* d_out, int out_size)
{
    const int*   seq  = (const int*)  d_in[0];
    const float* emb  = (const float*)d_in[1];
    const float* pes  = (const float*)d_in[2];
    const float* wq   = (const float*)d_in[3];
    const float* bq   = (const float*)d_in[4];
    const float* wk   = (const float*)d_in[5];
    const float* bk   = (const float*)d_in[6];
    const float* wv   = (const float*)d_in[7];
    const float* bv   = (const float*)d_in[8];
    const float* wo   = (const float*)d_in[9];
    const float* bo   = (const float*)d_in[10];
    const float* agam = (const float*)d_in[11];
    const float* abet = (const float*)d_in[12];
    const float* amea = (const float*)d_in[13];
    const float* avar = (const float*)d_in[14];
    const float* w1   = (const float*)d_in[15];
    const float* bff1 = (const float*)d_in[16];
    const float* w2   = (const float*)d_in[17];
    const float* bff2 = (const float*)d_in[18];
    const float* fgam = (const float*)d_in[19];
    const float* fbet = (const float*)d_in[20];
    const float* fmea = (const float*)d_in[21];
    const float* fvar = (const float*)d_in[22];
    float* out = (float*)d_out;

    float *x, *qkv, *p, *h, *f, *vt, *w1t, *w2t, *wot, *wqkvt, *bqkv;
    cudaGetSymbolAddress((void**)&x, g_x);
    cudaGetSymbolAddress((void**)&qkv, g_qkv);
    cudaGetSymbolAddress((void**)&p, g_p);
    cudaGetSymbolAddress((void**)&h, g_h);
    cudaGetSymbolAddress((void**)&f, g_f);
    cudaGetSymbolAddress((void**)&vt, g_vt);
    cudaGetSymbolAddress((void**)&w1t, g_w1t);
    cudaGetSymbolAddress((void**)&w2t, g_w2t);
    cudaGetSymbolAddress((void**)&wot, g_wot);
    cudaGetSymbolAddress((void**)&wqkvt, g_wqkvt);
    cudaGetSymbolAddress((void**)&bqkv, g_bqkv);

    // dynamic smem: stages * (A + B) floats * 4B
    const int SM128 = STAGES * (128 * 36 + 128 * 36) * 4;   // 110592
    const int SM64  = STAGES * (128 * 36 + 64 * 36) * 4;    // 82944
    cudaFuncSetAttribute(wgemm<128>, cudaFuncAttributeMaxDynamicSharedMemorySize, SM128);
    cudaFuncSetAttribute(wgemm<64>,  cudaFuncAttributeMaxDynamicSharedMemorySize, SM64);

    dim3 tb(32, 8);
    // weight preprocessing (every replay; deterministic)
    transpose_k<<<dim3(FF_ / 32, D_ / 32, L_), tb>>>(w1, w1t, D_, FF_, FF_,
                                                     (long)D_ * FF_, (long)D_ * FF_);
    transpose_k<<<dim3(D_ / 32, FF_ / 32, L_), tb>>>(w2, w2t, FF_, D_, D_,
                                                     (long)D_ * FF_, (long)D_ * FF_);
    transpose_k<<<dim3(D_ / 32, DK_ / 32, L_), tb>>>(wo, wot, DK_, D_, D_,
                                                     (long)DK_ * D_, (long)DK_ * D_);
    qkvpack<<<dim3(D_ / 256, NQKV, L_), 256>>>(wq, wk, wv, bq, bk, bv, wqkvt, bqkv);

    embed_kernel<<<BS_, 256>>>(seq, emb, pes, x);

    for (int l = 0; l < L_; l++) {
        const float* w1tl = w1t + (long)l * FF_ * D_;
        const float* w2tl = w2t + (long)l * D_ * FF_;
        const float* wotl = wot + (long)l * D_ * DK_;
        const float* wqkvtl = wqkvt + (long)l * NQKV * D_;
        const float* bqkvl = bqkv + l * NQKV;

        // QKV: qkv[4096,256] = x @ wqkvt^T + bqkv
        wgemm<128><<<dim3(NQKV / 128, BS_ / 128, 1), 256, SM128>>>(
            x, D_, wqkvtl, D_, bqkvl, qkv, NQKV, D_, 0, 0, 0,
            0, nullptr, nullptr, nullptr, nullptr, nullptr);

        // scores: p[b,512,512] = 0.125 * q @ k^T
        wgemm<128><<<dim3(S_ / 128, S_ / 128, B_), 256, SM128>>>(
            qkv, NQKV, qkv + 64, NQKV, nullptr, p, S_, DK_,
            (long)S_ * NQKV, (long)S_ * NQKV, (long)S_ * S_,
            3, nullptr, nullptr, nullptr, nullptr, nullptr);

        softmax512<<<B_ * S_, 256>>>(p);

        // V^T per batch: vt[b][64][512] <- qkv[b*512:, 128:192]
        transpose_k<<<dim3(DK_ / 32, S_ / 32, B_), tb>>>(
            qkv + 128, vt, S_, DK_, NQKV, (long)S_ * NQKV, (long)DK_ * S_);

        // head: h[b,512,64] = p @ v
        wgemm<64><<<dim3(1, S_ / 128, B_), 256, SM64>>>(
            p, S_, vt, S_, nullptr, h, DK_, S_,
            (long)S_ * S_, (long)DK_ * S_, (long)S_ * DK_,
            0, nullptr, nullptr, nullptr, nullptr, nullptr);

        // att out + residual + BN: x = BN(x + h @ wo + bo)
        wgemm<128><<<dim3(D_ / 128, BS_ / 128, 1), 256, SM128>>>(
            h, DK_, wotl, DK_, bo + l * D_, x, D_, DK_, 0, 0, 0,
            2, x, agam + l * D_, abet + l * D_, amea + l * D_, avar + l * D_);

        // FFN1: f = relu(x @ w1 + b1)
        wgemm<128><<<dim3(FF_ / 128, BS_ / 128, 1), 256, SM128>>>(
            x, D_, w1tl, D_, bff1 + l * FF_, f, FF_, D_, 0, 0, 0,
            1, nullptr, nullptr, nullptr, nullptr, nullptr);

        // FFN2 + residual + BN
        float* dst = (l == L_ - 1) ? out : x;
        wgemm<128><<<dim3(D_ / 128, BS_ / 128, 1), 256, SM128>>>(
            f, FF_, w2tl, FF_, bff2 + l * D_, dst, D_, FF_, 0, 0, 0,
            2, x, fgam + l * D_, fbet + l * D_, fmea + l * D_, fvar + l * D_);
    }
}

// round 5
// speedup vs baseline: 6.6397x; 4.2409x over previous
#include <cuda_runtime.h>
#include <cuda_fp16.h>
#include <mma.h>
#include <math.h>
#include <stdint.h>

using namespace nvcuda;

// Problem dims
#define L_   4
#define D_   1024
#define DK_  64
#define B_   8
#define S_   512
#define FF_  4096
#define BS_  (B_ * S_)           // 4096 rows
#define NQKV 256                 // padded q|k|v concat width
#define EPS_ 1e-3f

// -------------------- scratch (device globals; no allocations) ---------------
__device__ float  g_x[BS_ * D_];             // activations fp32 (residual source)
__device__ __half g_xh[BS_ * D_];            // activations half (GEMM A)
__device__ __half g_qkvh[BS_ * NQKV];        // q|k|v|pad half
__device__ float  g_p[B_ * S_ * S_];         // scores fp32
__device__ __half g_ph[B_ * S_ * S_];        // probs half
__device__ __half g_hh[BS_ * DK_];           // head out half
__device__ __half g_fh[BS_ * FF_];           // ffn hidden half
__device__ __half g_vt[B_ * DK_ * S_];       // V^T per batch [64,512] half
__device__ __half g_w1t[L_ * FF_ * D_];      // w1^T half
__device__ __half g_w2t[L_ * D_ * FF_];      // w2^T half
__device__ __half g_wot[L_ * D_ * DK_];      // wo^T half
__device__ __half g_wqkvt[L_ * NQKV * D_];   // packed qkv^T half
__device__ float  g_bqkv[L_ * NQKV];

__device__ __forceinline__ uint32_t smem_u32(const void* p) {
    uint32_t a;
    asm("{ .reg .u64 t; cvta.to.shared.u64 t, %1; cvt.u32.u64 %0, t; }" : "=r"(a) : "l"(p));
    return a;
}

// ======================= wmma FP16 pipelined GEMM ============================
// C[M, N] = A[M, K(ldA)] @ Bt[N, K(ldB)]^T   (A, Bt half; Bt K-major)
// CTA tile 128 x BN, K chunk 64, 3-stage cp.async pipeline, 8 warps (4m x 2n),
// warp tile 32 x (BN/2), wmma m16n16k16 fp16 -> fp32 accum.
// Outputs: Cf (fp32, optional) and Ch (half, optional), both [M, N].
// mode 0: +bias   1: +bias, relu   2: BN(res + bias + acc)   3: acc * 0.125
#define STAGES 3

template<int BN>
__global__ void __launch_bounds__(256, 2) wgemm(
    const __half* __restrict__ A, int ldA,
    const __half* __restrict__ Bt, int ldB,
    const float* __restrict__ bias,
    float* __restrict__ Cf, __half* __restrict__ Ch,
    int N, int K, long sA, long sB, long sC,
    int mode,
    const float* __restrict__ res,
    const float* __restrict__ gamma, const float* __restrict__ beta,
    const float* __restrict__ mean,  const float* __restrict__ var)
{
    constexpr int BM = 128, BK = 64, LDSH = BK + 8;    // 72 halves/row (144B)
    constexpr int A_STG = BM * LDSH;                   // halves
    constexpr int B_STG = BN * LDSH;
    constexpr int STG = A_STG + B_STG;
    constexpr int WN = BN / 2;
    constexpr int NT = WN / 16;

    extern __shared__ char smraw[];
    __half* sm = (__half*)smraw;

    const int tid = threadIdx.x;
    const int wid = tid >> 5;
    const int warp_m = wid & 3;
    const int warp_n = wid >> 2;
    const int m0 = blockIdx.y * BM;
    const int n0 = blockIdx.x * BN;
    const int bz = blockIdx.z;
    A += bz * sA; Bt += bz * sB;
    if (Cf)  Cf += bz * sC;
    if (Ch)  Ch += bz * sC;
    if (res) res += bz * sC;

    const int NK = K >> 6;

    auto load_chunk = [&](int chunk, int stage) {
        __half* smA = sm + stage * STG;
        __half* smB = smA + A_STG;
        const __half* gA = A + (long)m0 * ldA + chunk * 64;
        const __half* gB = Bt + (long)n0 * ldB + chunk * 64;
        #pragma unroll
        for (int j = 0; j < 4; j++) {               // A: 128 rows x 8 x 16B
            int idx = tid + j * 256;
            int r = idx >> 3, c8 = (idx & 7) * 8;
            uint32_t dst = smem_u32(&smA[r * LDSH + c8]);
            const __half* src = gA + (long)r * ldA + c8;
            asm volatile("cp.async.cg.shared.global [%0], [%1], 16;" :: "r"(dst), "l"(src));
        }
        #pragma unroll
        for (int j = 0; j < BN / 32; j++) {         // B: BN rows x 8 x 16B
            int idx = tid + j * 256;
            int r = idx >> 3, c8 = (idx & 7) * 8;
            uint32_t dst = smem_u32(&smB[r * LDSH + c8]);
            const __half* src = gB + (long)r * ldB + c8;
            asm volatile("cp.async.cg.shared.global [%0], [%1], 16;" :: "r"(dst), "l"(src));
        }
        asm volatile("cp.async.commit_group;" ::: "memory");
    };

    wmma::fragment<wmma::accumulator, 16, 16, 16, float> acc[2][NT];
    #pragma unroll
    for (int i = 0; i < 2; i++)
        #pragma unroll
        for (int j = 0; j < NT; j++) wmma::fill_fragment(acc[i][j], 0.f);

    load_chunk(0, 0);
    if (NK > 1) load_chunk(1, 1);

    for (int i = 0; i < NK; i++) {
        if (i < NK - 1) asm volatile("cp.async.wait_group 1;" ::: "memory");
        else            asm volatile("cp.async.wait_group 0;" ::: "memory");
        __syncthreads();                 // chunk i resident; stage (i+2)%3 free

        if (i + 2 < NK) load_chunk(i + 2, (i + 2) % STAGES);

        const __half* sA = sm + (i % STAGES) * STG;
        const __half* sB = sA + A_STG;

        #pragma unroll
        for (int ks = 0; ks < 4; ks++) {
            int kk = ks * 16;
            wmma::fragment<wmma::matrix_a, 16, 16, 16, __half, wmma::row_major> af[2];
            wmma::fragment<wmma::matrix_b, 16, 16, 16, __half, wmma::col_major> bf[NT];
            #pragma unroll
            for (int mi = 0; mi < 2; mi++)
                wmma::load_matrix_sync(af[mi], sA + (warp_m * 32 + mi * 16) * LDSH + kk, LDSH);
            #pragma unroll
            for (int nj = 0; nj < NT; nj++)
                wmma::load_matrix_sync(bf[nj], sB + (warp_n * WN + nj * 16) * LDSH + kk, LDSH);
            #pragma unroll
            for (int mi = 0; mi < 2; mi++)
                #pragma unroll
                for (int nj = 0; nj < NT; nj++)
                    wmma::mma_sync(acc[mi][nj], af[mi], bf[nj], acc[mi][nj]);
        }
    }
    __syncthreads();

    // ---------------- epilogue: fp32 staging in smem, fused ops --------------
    float* stg = (float*)smraw;
    #pragma unroll
    for (int mi = 0; mi < 2; mi++)
        #pragma unroll
        for (int nj = 0; nj < NT; nj++)
            wmma::store_matrix_sync(
                stg + (long)(warp_m * 32 + mi * 16) * BN + warp_n * WN + nj * 16,
                acc[mi][nj], BN, wmma::mem_row_major);
    __syncthreads();

    #pragma unroll
    for (int it = 0; it < BM * BN / 4 / 256; it++) {
        int idx = (tid + it * 256) * 4;
        int r = idx / BN, c = idx % BN;
        int gc = n0 + c;
        float4 o = *(const float4*)&stg[idx];
        if (bias) {
            float4 bb = *(const float4*)&bias[gc];
            o.x += bb.x; o.y += bb.y; o.z += bb.z; o.w += bb.w;
        }
        if (mode == 1) {
            o.x = fmaxf(o.x, 0.f); o.y = fmaxf(o.y, 0.f);
            o.z = fmaxf(o.z, 0.f); o.w = fmaxf(o.w, 0.f);
        } else if (mode == 2) {
            float4 rr = *(const float4*)&res[(long)(m0 + r) * N + gc];
            float4 gg = *(const float4*)&gamma[gc];
            float4 be = *(const float4*)&beta[gc];
            float4 mm = *(const float4*)&mean[gc];
            float4 va = *(const float4*)&var[gc];
            o.x = gg.x * (o.x + rr.x - mm.x) * rsqrtf(va.x + EPS_) + be.x;
            o.y = gg.y * (o.y + rr.y - mm.y) * rsqrtf(va.y + EPS_) + be.y;
            o.z = gg.z * (o.z + rr.z - mm.z) * rsqrtf(va.z + EPS_) + be.z;
            o.w = gg.w * (o.w + rr.w - mm.w) * rsqrtf(va.w + EPS_) + be.w;
        } else if (mode == 3) {
            o.x *= 0.125f; o.y *= 0.125f; o.z *= 0.125f; o.w *= 0.125f;
        }
        long off = (long)(m0 + r) * N + gc;
        if (Cf) *(float4*)&Cf[off] = o;
        if (Ch) {
            __half2 h0 = __floats2half2_rn(o.x, o.y);
            __half2 h1 = __floats2half2_rn(o.z, o.w);
            *(uint2*)&Ch[off] = make_uint2(*(uint32_t*)&h0, *(uint32_t*)&h1);
        }
    }
}

// ======================= small prep / misc kernels ===========================
__global__ void __launch_bounds__(256) embed_kernel(
    const int* __restrict__ seq, const float* __restrict__ emb,
    const float* __restrict__ pes, float* __restrict__ x, __half* __restrict__ xh)
{
    int bs = blockIdx.x;
    int s  = bs & (S_ - 1);
    int tok = seq[bs];
    float p = pes[(long)s * D_];
    const float4* e = (const float4*)(emb + (long)tok * D_);
    float4 v = e[threadIdx.x];
    v.x += p; v.y += p; v.z += p; v.w += p;
    ((float4*)(x + (long)bs * D_))[threadIdx.x] = v;
    __half2 h0 = __floats2half2_rn(v.x, v.y);
    __half2 h1 = __floats2half2_rn(v.z, v.w);
    ((uint2*)(xh + (long)bs * D_))[threadIdx.x] = make_uint2(*(uint32_t*)&h0, *(uint32_t*)&h1);
}

// fp32 -> half transpose: out[c][r] = in[r][c]; batched by blockIdx.z
__global__ void __launch_bounds__(256) transpose_f2h(
    const float* __restrict__ in, __half* __restrict__ out,
    int R, int C, int ldIn, long sIn, long sOut)
{
    __shared__ float t[32][33];
    in += (long)blockIdx.z * sIn; out += (long)blockIdx.z * sOut;
    int c0 = blockIdx.x * 32, r0 = blockIdx.y * 32;
    int tx = threadIdx.x, ty = threadIdx.y;
    #pragma unroll
    for (int j = 0; j < 32; j += 8)
        t[ty + j][tx] = in[(long)(r0 + ty + j) * ldIn + c0 + tx];
    __syncthreads();
    #pragma unroll
    for (int j = 0; j < 32; j += 8)
        out[(long)(c0 + ty + j) * R + r0 + tx] = __float2half_rn(t[tx][ty + j]);
}

// half -> half transpose
__global__ void __launch_bounds__(256) transpose_h2h(
    const __half* __restrict__ in, __half* __restrict__ out,
    int R, int C, int ldIn, long sIn, long sOut)
{
    __shared__ __half t[32][34];
    in += (long)blockIdx.z * sIn; out += (long)blockIdx.z * sOut;
    int c0 = blockIdx.x * 32, r0 = blockIdx.y * 32;
    int tx = threadIdx.x, ty = threadIdx.y;
    #pragma unroll
    for (int j = 0; j < 32; j += 8)
        t[ty + j][tx] = in[(long)(r0 + ty + j) * ldIn + c0 + tx];
    __syncthreads();
    #pragma unroll
    for (int j = 0; j < 32; j += 8)
        out[(long)(c0 + ty + j) * R + r0 + tx] = t[tx][ty + j];
}

// pack wq|wk|wv -> half wqkvt [L][256][1024] (transposed) + fp32 bias pack
__global__ void __launch_bounds__(256) qkvpack(
    const float* __restrict__ wq, const float* __restrict__ wk,
    const float* __restrict__ wv, const float* __restrict__ bq,
    const float* __restrict__ bk, const float* __restrict__ bv,
    __half* __restrict__ wt, float* __restrict__ bt)
{
    int l = blockIdx.z;
    int n = blockIdx.y;                         // 0..255
    int k = blockIdx.x * 256 + threadIdx.x;     // 0..1023
    const float* src = (n < 64) ? wq : (n < 128) ? wk : (n < 192) ? wv : nullptr;
    int j = n & 63;
    float v = 0.f;
    if (src) v = src[((long)l * D_ + k) * DK_ + j];
    wt[((long)l * NQKV + n) * D_ + k] = __float2half_rn(v);
    if (blockIdx.x == 0 && threadIdx.x == 0) {
        const float* bs = (n < 64) ? bq : (n < 128) ? bk : (n < 192) ? bv : nullptr;
        bt[l * NQKV + n] = bs ? bs[l * DK_ + j] : 0.f;
    }
}

// softmax over 512 fp32 scores -> half probs
__global__ void __launch_bounds__(256) softmax512(
    const float* __restrict__ p, __half* __restrict__ ph)
{
    __shared__ float red[256];
    const float* r = p + (long)blockIdx.x * S_;
    __half* o = ph + (long)blockIdx.x * S_;
    int t = threadIdx.x;
    float a = r[t], b = r[t + 256];
    red[t] = fmaxf(a, b);
    __syncthreads();
    for (int s = 128; s > 0; s >>= 1) {
        if (t < s) red[t] = fmaxf(red[t], red[t + s]);
        __syncthreads();
    }
    float m = red[0];
    __syncthreads();
    float ea = __expf(a - m), eb = __expf(b - m);
    red[t] = ea + eb;
    __syncthreads();
    for (int s = 128; s > 0; s >>= 1) {
        if (t < s) red[t] += red[t + s];
        __syncthreads();
    }
    float inv = 1.0f / red[0];
    o[t] = __float2half_rn(ea * inv);
    o[t + 256] = __float2half_rn(eb * inv);
}

// ------------------------------------------------------------------------------
extern "C" void kernel_launch(void* const* d_in, const int* in_sizes, int n_in,
                              void* d_out, int out_size)
{
    const int*   seq  = (const int*)  d_in[0];
    const float* emb  = (const float*)d_in[1];
    const float* pes  = (const float*)d_in[2];
    const float* wq   = (const float*)d_in[3];
    const float* bq   = (const float*)d_in[4];
    const float* wk   = (const float*)d_in[5];
    const float* bk   = (const float*)d_in[6];
    const float* wv   = (const float*)d_in[7];
    const float* bv   = (const float*)d_in[8];
    const float* wo   = (const float*)d_in[9];
    const float* bo   = (const float*)d_in[10];
    const float* agam = (const float*)d_in[11];
    const float* abet = (const float*)d_in[12];
    const float* amea = (const float*)d_in[13];
    const float* avar = (const float*)d_in[14];
    const float* w1   = (const float*)d_in[15];
    const float* bff1 = (const float*)d_in[16];
    const float* w2   = (const float*)d_in[17];
    const float* bff2 = (const float*)d_in[18];
    const float* fgam = (const float*)d_in[19];
    const float* fbet = (const float*)d_in[20];
    const float* fmea = (const float*)d_in[21];
    const float* fvar = (const float*)d_in[22];
    float* out = (float*)d_out;

    float *x, *p, *bqkv;
    __half *xh, *qkvh, *ph, *hh, *fh, *vt, *w1t, *w2t, *wot, *wqkvt;
    cudaGetSymbolAddress((void**)&x, g_x);
    cudaGetSymbolAddress((void**)&xh, g_xh);
    cudaGetSymbolAddress((void**)&qkvh, g_qkvh);
    cudaGetSymbolAddress((void**)&p, g_p);
    cudaGetSymbolAddress((void**)&ph, g_ph);
    cudaGetSymbolAddress((void**)&hh, g_hh);
    cudaGetSymbolAddress((void**)&fh, g_fh);
    cudaGetSymbolAddress((void**)&vt, g_vt);
    cudaGetSymbolAddress((void**)&w1t, g_w1t);
    cudaGetSymbolAddress((void**)&w2t, g_w2t);
    cudaGetSymbolAddress((void**)&wot, g_wot);
    cudaGetSymbolAddress((void**)&wqkvt, g_wqkvt);
    cudaGetSymbolAddress((void**)&bqkv, g_bqkv);

    // dynamic smem: max(3 * (128+BN)*72 halves * 2B, 128*BN*4B epilogue)
    const int SM128 = 3 * (128 + 128) * 72 * 2;     // 110592
    const int SM64  = 3 * (128 + 64) * 72 * 2;      // 82944
    cudaFuncSetAttribute(wgemm<128>, cudaFuncAttributeMaxDynamicSharedMemorySize, SM128);
    cudaFuncSetAttribute(wgemm<64>,  cudaFuncAttributeMaxDynamicSharedMemorySize, SM64);

    dim3 tb(32, 8);
    // weight preprocessing (every replay; deterministic)
    transpose_f2h<<<dim3(FF_ / 32, D_ / 32, L_), tb>>>(w1, w1t, D_, FF_, FF_,
                                                       (long)D_ * FF_, (long)D_ * FF_);
    transpose_f2h<<<dim3(D_ / 32, FF_ / 32, L_), tb>>>(w2, w2t, FF_, D_, D_,
                                                       (long)D_ * FF_, (long)D_ * FF_);
    transpose_f2h<<<dim3(D_ / 32, DK_ / 32, L_), tb>>>(wo, wot, DK_, D_, D_,
                                                       (long)DK_ * D_, (long)DK_ * D_);
    qkvpack<<<dim3(D_ / 256, NQKV, L_), 256>>>(wq, wk, wv, bq, bk, bv, wqkvt, bqkv);

    embed_kernel<<<BS_, 256>>>(seq, emb, pes, x, xh);

    for (int l = 0; l < L_; l++) {
        const __half* w1tl = w1t + (long)l * FF_ * D_;
        const __half* w2tl = w2t + (long)l * D_ * FF_;
        const __half* wotl = wot + (long)l * D_ * DK_;
        const __half* wqkvtl = wqkvt + (long)l * NQKV * D_;
        const float* bqkvl = bqkv + l * NQKV;

        // QKV: qkvh[4096,256] = xh @ wqkvt^T + bqkv
        wgemm<128><<<dim3(NQKV / 128, BS_ / 128, 1), 256, SM128>>>(
            xh, D_, wqkvtl, D_, bqkvl, nullptr, qkvh, NQKV, D_, 0, 0, 0,
            0, nullptr, nullptr, nullptr, nullptr, nullptr);

        // scores: p[b,512,512] = 0.125 * q @ k^T
        wgemm<128><<<dim3(S_ / 128, S_ / 128, B_), 256, SM128>>>(
            qkvh, NQKV, qkvh + 64, NQKV, nullptr, p, nullptr, S_, DK_,
            (long)S_ * NQKV, (long)S_ * NQKV, (long)S_ * S_,
            3, nullptr, nullptr, nullptr, nullptr, nullptr);

        softmax512<<<B_ * S_, 256>>>(p, ph);

        // V^T per batch: vt[b][64][512] <- qkvh[b*512:, 128:192]
        transpose_h2h<<<dim3(DK_ / 32, S_ / 32, B_), tb>>>(
            qkvh + 128, vt, S_, DK_, NQKV, (long)S_ * NQKV, (long)DK_ * S_);

        // head: hh[b,512,64] = ph @ v
        wgemm<64><<<dim3(1, S_ / 128, B_), 256, SM64>>>(
            ph, S_, vt, S_, nullptr, nullptr, hh, DK_, S_,
            (long)S_ * S_, (long)DK_ * S_, (long)S_ * DK_,
            0, nullptr, nullptr, nullptr, nullptr, nullptr);

        // att out + residual + BN: x = BN(x + hh @ wo + bo)  (fp32 + half copies)
        wgemm<128><<<dim3(D_ / 128, BS_ / 128, 1), 256, SM128>>>(
            hh, DK_, wotl, DK_, bo + l * D_, x, xh, D_, DK_, 0, 0, 0,
            2, x, agam + l * D_, abet + l * D_, amea + l * D_, avar + l * D_);

        // FFN1: fh = relu(xh @ w1 + b1)
        wgemm<128><<<dim3(FF_ / 128, BS_ / 128, 1), 256, SM128>>>(
            xh, D_, w1tl, D_, bff1 + l * FF_, nullptr, fh, FF_, D_, 0, 0, 0,
            1, nullptr, nullptr, nullptr, nullptr, nullptr);

        // FFN2 + residual + BN
        float* dst = (l == L_ - 1) ? out : x;
        wgemm<128><<<dim3(D_ / 128, BS_ / 128, 1), 256, SM128>>>(
            fh, FF_, w2tl, FF_, bff2 + l * D_, dst, xh, D_, FF_, 0, 0, 0,
            2, x, fgam + l * D_, fbet + l * D_, fmea + l * D_, fvar + l * D_);
    }
}